// round 1
// baseline (speedup 1.0000x reference)
#include <cuda_runtime.h>

// CTC loss (scaled forward algorithm, linear domain) for
// B=512, T=512, C=256, L=64, S=129, blank = C-1.
// One warp per batch; state s = 32*k + lane (k=0..4, valid s<129).

#define TT 512
#define CC 256
#define BB 512
#define LL 64
#define SS 129
#define EPSF 1e-7f

__global__ __launch_bounds__(32, 16)
void ctc_scaled_kernel(const int* __restrict__ y_true,
                       const float* __restrict__ y_pred,
                       float* __restrict__ out)
{
    const int b    = blockIdx.x;
    const int lane = threadIdx.x;
    const unsigned FULL = 0xFFFFFFFFu;

    const float* __restrict__ yp = y_pred + (size_t)b * TT * CC;
    const int*   __restrict__ lab = y_true + b * LL;

    // ---- per-(lane,k) static state metadata ----
    // ext[s] = (s odd) ? lab[(s-1)/2] : blank
    // skip[s] = (s odd) && (s>=3) && lab[(s-1)/2] != lab[(s-3)/2]
    int   cls[5];
    float skipf[5];
#pragma unroll
    for (int k = 0; k < 5; k++) {
        int s = 32 * k + lane;
        bool valid = (s < SS);
        if (valid && (s & 1)) {
            int idx = (s - 1) >> 1;
            int cl  = lab[idx];
            cls[k]  = cl;
            if (s >= 3) {
                int cl2 = lab[idx - 1];
                skipf[k] = (cl != cl2) ? 1.0f : 0.0f;
            } else {
                skipf[k] = 0.0f;
            }
        } else {
            cls[k]  = CC - 1;   // blank (also safe dummy for invalid states)
            skipf[k] = 0.0f;
        }
    }

    // ---- t = 0 init: only states 0 (blank) and 1 (first label) ----
    float a[5];
#pragma unroll
    for (int k = 0; k < 5; k++) a[k] = 0.0f;
    if (lane < 2) a[0] = yp[cls[0]] + EPSF;   // lane0: blank@t0, lane1: lab[0]@t0

    // ---- prefetch p for t = 1..4 ----
    float pb[4][5];
#pragma unroll
    for (int j = 0; j < 4; j++) {
#pragma unroll
        for (int k = 0; k < 5; k++)
            pb[j][k] = yp[(1 + j) * CC + cls[k]];
    }

    int E = 0;                      // accumulated power-of-2 rescale exponent
    const int lm1 = (lane + 31) & 31;
    const int lm2 = (lane + 30) & 31;

    for (int t0 = 1; t0 < TT; t0 += 4) {
#pragma unroll
        for (int j = 0; j < 4; j++) {
            int t = t0 + j;
            if (t < TT) {
                // halo exchange on previous-step alphas
                float r1[5], r2[5];
#pragma unroll
                for (int k = 0; k < 5; k++) r1[k] = __shfl_sync(FULL, a[k], lm1);
#pragma unroll
                for (int k = 0; k < 5; k++) r2[k] = __shfl_sync(FULL, a[k], lm2);

                float na[5];
#pragma unroll
                for (int k = 0; k < 5; k++) {
                    // a[s-1]
                    float u1 = r1[k];
                    if (lane == 0) u1 = (k > 0) ? r1[k - 1] : 0.0f;
                    // a[s-2]
                    float u2 = r2[k];
                    if (lane < 2)  u2 = (k > 0) ? r2[k - 1] : 0.0f;

                    float sum = a[k] + u1 + skipf[k] * u2;
                    na[k] = sum * (pb[j][k] + EPSF);
                }
#pragma unroll
                for (int k = 0; k < 5; k++) a[k] = na[k];

                // prefetch t+4 into the slot just consumed
                if (t + 4 < TT) {
#pragma unroll
                    for (int k = 0; k < 5; k++)
                        pb[j][k] = yp[(t + 4) * CC + cls[k]];
                }
            }
        }

        // ---- exact power-of-2 rescale once per 4 steps ----
        float m = a[0];
#pragma unroll
        for (int k = 1; k < 5; k++) m = fmaxf(m, a[k]);
#pragma unroll
        for (int o = 16; o > 0; o >>= 1)
            m = fmaxf(m, __shfl_xor_sync(FULL, m, o));
        int e = (__float_as_int(m) >> 23) & 255;       // biased exponent of max
        float sc = __int_as_float((254 - e) << 23);    // 2^(127-e), exact
        E += e - 127;
#pragma unroll
        for (int k = 0; k < 5; k++) a[k] *= sc;
    }

    // ---- loss = -log(alphaT[S-1] + alphaT[S-2]) with scale restored ----
    float v127 = __shfl_sync(FULL, a[3], 31);   // state 127 = 32*3 + 31
    float v128 = __shfl_sync(FULL, a[4], 0);    // state 128 = 32*4 + 0
    if (lane == 0) {
        out[b] = -(logf(v127 + v128) + (float)E * 0.69314718055994530942f);
    }
}

extern "C" void kernel_launch(void* const* d_in, const int* in_sizes, int n_in,
                              void* d_out, int out_size)
{
    // inputs: y_true int32 [512,64] (32768 elems), y_pred float32 [512,512,256]
    const int*   y_true;
    const float* y_pred;
    if (in_sizes[0] == BB * LL) {
        y_true = (const int*)d_in[0];
        y_pred = (const float*)d_in[1];
    } else {
        y_true = (const int*)d_in[1];
        y_pred = (const float*)d_in[0];
    }
    float* out = (float*)d_out;

    ctc_scaled_kernel<<<BB, 32>>>(y_true, y_pred, out);
}